// round 16
// baseline (speedup 1.0000x reference)
#include <cuda_runtime.h>
#include <cstdint>
#include <cstddef>

#define BB 1024
#define FF 4096
#define DD 32
#define NT 4
#define KSPLITS 32
#define K_PER_ITEM 128
#define M_PER_ITEM 32
#define MT (BB / M_PER_ITEM)          // 32 row-tiles
#define ITEMS (MT * KSPLITS)          // 1024
#define KC 32
#define NCHUNK 4
#define A_STRIDE 132                  // conflict-free, 16B aligned
#define B_STRIDE 40                   // 0-31 embed, 32 bias
#define NBP 36                        // partials row stride
#define NCTAS 304                     // 2 per SM on 152 SMs
#define SMEM_FLOATS (M_PER_ITEM * A_STRIDE + K_PER_ITEM * B_STRIDE)  // 9344 -> 37.4 KB

__device__ float g_part[(size_t)KSPLITS * BB * NBP];
__device__ unsigned g_ticket;          // reset to 0 by finisher each replay

__device__ __forceinline__ uint32_t smem_u32(const void* p) {
    uint32_t a;
    asm("{ .reg .u64 t; cvta.to.shared.u64 t, %1; cvt.u32.u64 %0, t; }" : "=r"(a) : "l"(p));
    return a;
}
__device__ __forceinline__ void cp16(uint32_t dst, const void* src) {
    asm volatile("cp.async.cg.shared.global [%0], [%1], 16;" :: "r"(dst), "l"(src));
}
__device__ __forceinline__ void cp4(uint32_t dst, const void* src) {
    asm volatile("cp.async.ca.shared.global [%0], [%1], 4;" :: "r"(dst), "l"(src));
}
__device__ __forceinline__ void cp_commit() { asm volatile("cp.async.commit_group;"); }
template <int N>
__device__ __forceinline__ void cp_wait() { asm volatile("cp.async.wait_group %0;" :: "n"(N)); }

// ---------------- persistent work-stealing GEMM ----------------
__global__ void __launch_bounds__(256, 2)
fm_gemm(const float* __restrict__ data,
        const float* __restrict__ embed,
        const float* __restrict__ bias)
{
    extern __shared__ float sm[];
    float* As = sm;                        // [row][k] 32 x stride 132
    float* Bs = sm + M_PER_ITEM * A_STRIDE; // [k][n]  128 x stride 40
    __shared__ unsigned s_id;

    const int t = threadIdx.x;
    const int w = t >> 5, lane = t & 31;
    const int g = lane >> 2, ctg = lane & 3;
    const int f  = w & 1;                  // m16 fragment (rows f*16..f*16+15)
    const int nt = w >> 1;                 // n-tile 0..3

    for (;;) {
        if (t == 0) s_id = atomicAdd(&g_ticket, 1u);
        __syncthreads();                   // also guards smem reuse across items
        const unsigned id = s_id;
        if (id >= ITEMS) break;

        const int mt = id & (MT - 1);
        const int ks = id >> 5;
        const int kbase = ks * K_PER_ITEM;
        const float* arow0 = data + (size_t)(mt * M_PER_ITEM) * FF + kbase;

        // issue all loads, one commit group per 32-k chunk
        #pragma unroll
        for (int c = 0; c < NCHUNK; c++) {
            {   // A: 32 rows x 8 float4
                const int row = t >> 3, kq = (t & 7) << 2;
                cp16(smem_u32(&As[row * A_STRIDE + c * KC + kq]),
                     arow0 + (size_t)row * FF + c * KC + kq);
            }
            {   // B: 32 k-rows x 8 float4
                const int k = t >> 3, q4 = (t & 7) << 2;
                cp16(smem_u32(&Bs[(c * KC + k) * B_STRIDE + q4]),
                     embed + (size_t)(kbase + c * KC + k) * DD + q4);
            }
            if (t < KC)
                cp4(smem_u32(&Bs[(c * KC + t) * B_STRIDE + 32]), bias + kbase + c * KC + t);
            cp_commit();
        }

        float acc[4] = {0.f, 0.f, 0.f, 0.f};
        float bacc0 = 0.f, bacc1 = 0.f;
        const float* Af = &As[f * 16 * A_STRIDE];

        #pragma unroll
        for (int ch = 0; ch < NCHUNK; ch++) {
            if (ch == 0)      cp_wait<3>();
            else if (ch == 1) cp_wait<2>();
            else if (ch == 2) cp_wait<1>();
            else              cp_wait<0>();
            __syncthreads();

            #pragma unroll
            for (int ksi = 0; ksi < 4; ksi++) {
                const int k0 = ch * KC + ksi * 8;
                const uint32_t a0 = __float_as_uint(Af[g * A_STRIDE + k0 + ctg]);
                const uint32_t a1 = __float_as_uint(Af[(g + 8) * A_STRIDE + k0 + ctg]);
                const uint32_t a2 = __float_as_uint(Af[g * A_STRIDE + k0 + ctg + 4]);
                const uint32_t a3 = __float_as_uint(Af[(g + 8) * A_STRIDE + k0 + ctg + 4]);

                if (nt == 0) {   // bias column via FFMA (warp-uniform branch)
                    const float bk  = Bs[(k0 + ctg) * B_STRIDE + 32];
                    const float bk4 = Bs[(k0 + ctg + 4) * B_STRIDE + 32];
                    bacc0 = fmaf(__uint_as_float(a0), bk,  bacc0);
                    bacc0 = fmaf(__uint_as_float(a2), bk4, bacc0);
                    bacc1 = fmaf(__uint_as_float(a1), bk,  bacc1);
                    bacc1 = fmaf(__uint_as_float(a3), bk4, bacc1);
                }

                const uint32_t b0 = __float_as_uint(Bs[(k0 + ctg) * B_STRIDE + nt * 8 + g]);
                const uint32_t b1 = __float_as_uint(Bs[(k0 + ctg + 4) * B_STRIDE + nt * 8 + g]);
                asm volatile(
                    "mma.sync.aligned.m16n8k8.row.col.f32.tf32.tf32.f32 "
                    "{%0,%1,%2,%3}, {%4,%5,%6,%7}, {%8,%9}, {%0,%1,%2,%3};"
                    : "+f"(acc[0]), "+f"(acc[1]), "+f"(acc[2]), "+f"(acc[3])
                    : "r"(a0), "r"(a1), "r"(a2), "r"(a3), "r"(b0), "r"(b1));
            }
        }

        // epilogue: plain stores into this ksplit's private slab
        float* pbase = g_part + (size_t)ks * BB * NBP;
        const int mbase = mt * M_PER_ITEM + f * 16;
        const int n0 = nt * 8 + 2 * ctg;
        pbase[(size_t)(mbase + g) * NBP + n0]         = acc[0];
        pbase[(size_t)(mbase + g) * NBP + n0 + 1]     = acc[1];
        pbase[(size_t)(mbase + g + 8) * NBP + n0]     = acc[2];
        pbase[(size_t)(mbase + g + 8) * NBP + n0 + 1] = acc[3];

        if (nt == 0) {
            bacc0 += __shfl_xor_sync(0xffffffffu, bacc0, 1);
            bacc0 += __shfl_xor_sync(0xffffffffu, bacc0, 2);
            bacc1 += __shfl_xor_sync(0xffffffffu, bacc1, 1);
            bacc1 += __shfl_xor_sync(0xffffffffu, bacc1, 2);
            if (ctg == 0) {
                pbase[(size_t)(mbase + g) * NBP + 32]     = bacc0;
                pbase[(size_t)(mbase + g + 8) * NBP + 32] = bacc1;
            }
        }
    }

    asm volatile("griddepcontrol.launch_dependents;");
}

// ---------------- finisher: PDL wait, reduce 32 ksplits, sigmoid, reset ticket ----------------
__global__ void __launch_bounds__(256)
fm_finish(const float* __restrict__ gbias, float* __restrict__ out)
{
    asm volatile("griddepcontrol.wait;" ::: "memory");

    const int w = threadIdx.x >> 5, lane = threadIdx.x & 31;
    const int row = blockIdx.x * 8 + w;

    float s = 0.f;
    #pragma unroll
    for (int k = 0; k < KSPLITS; k++)
        s += g_part[((size_t)k * BB + row) * NBP + lane];

    const float b = g_part[((size_t)lane * BB + row) * NBP + 32];  // lane = ksplit

    float v = s * s + b;
    #pragma unroll
    for (int o = 16; o; o >>= 1)
        v += __shfl_xor_sync(0xffffffffu, v, o);

    if (lane == 0)
        out[row] = 1.0f / (1.0f + __expf(-(gbias[0] + v)));

    if (blockIdx.x == 0 && threadIdx.x == 0)
        g_ticket = 0u;                  // reset for next graph replay
}

extern "C" void kernel_launch(void* const* d_in, const int* in_sizes, int n_in,
                              void* d_out, int out_size)
{
    const float* data  = (const float*)d_in[0];
    const float* embed = (const float*)d_in[1];
    const float* bias  = (const float*)d_in[2];
    const float* gb    = (const float*)d_in[3];
    float* out = (float*)d_out;

    const int smem_bytes = SMEM_FLOATS * (int)sizeof(float);
    cudaFuncSetAttribute(fm_gemm, cudaFuncAttributeMaxDynamicSharedMemorySize, smem_bytes);

    fm_gemm<<<NCTAS, 256, smem_bytes>>>(data, embed, bias);

    cudaLaunchConfig_t cfg = {};
    cfg.gridDim = dim3(BB / 8);
    cfg.blockDim = dim3(256);
    cfg.dynamicSmemBytes = 0;
    cfg.stream = 0;
    cudaLaunchAttribute attr[1];
    attr[0].id = cudaLaunchAttributeProgrammaticStreamSerialization;
    attr[0].val.programmaticStreamSerializationAllowed = 1;
    cfg.attrs = attr;
    cfg.numAttrs = 1;
    cudaLaunchKernelEx(&cfg, fm_finish, gb, out);
}